// round 1
// baseline (speedup 1.0000x reference)
#include <cuda_runtime.h>
#include <cuda_bf16.h>

#define NN 100000
#define NE 1600000
#define F_IN 128
#define F_HID 128
#define F_CLS 64

// Scratch (no cudaMalloc allowed): device globals.
__device__ float g_deg_out[NN];
__device__ float g_deg_in[NN];
__device__ float g_agg1[(size_t)NN * F_IN];
__device__ float g_h[(size_t)NN * F_HID];
__device__ float g_agg2[(size_t)NN * F_HID];

// ---------------------------------------------------------------------------
// Zero all scratch that gets accumulated into.
// ---------------------------------------------------------------------------
__global__ void zero_kernel() {
    size_t i = (size_t)blockIdx.x * blockDim.x + threadIdx.x;
    size_t stride = (size_t)gridDim.x * blockDim.x;
    const size_t n4 = (size_t)NN * 128 / 4;
    float4 z = make_float4(0.f, 0.f, 0.f, 0.f);
    for (size_t j = i; j < n4; j += stride) {
        ((float4*)g_agg1)[j] = z;
        ((float4*)g_agg2)[j] = z;
    }
    for (size_t j = i; j < NN; j += stride) {
        g_deg_out[j] = 0.f;
        g_deg_in[j]  = 0.f;
    }
}

// ---------------------------------------------------------------------------
// Degrees: float atomic adds of 1.0 are exact integers -> deterministic.
// ---------------------------------------------------------------------------
__global__ void degree_kernel(const int* __restrict__ src,
                              const int* __restrict__ dst) {
    int e = blockIdx.x * blockDim.x + threadIdx.x;
    if (e < NE) {
        atomicAdd(&g_deg_out[src[e]], 1.0f);
        atomicAdd(&g_deg_in[dst[e]],  1.0f);
    }
}

// ---------------------------------------------------------------------------
// Scatter: one warp per edge. Lane l handles floats [4l, 4l+4).
// agg[dst] += x[src] * rsqrt(max(deg_out[src],1))
// Uses red.global.add.v4.f32 (sm_90+) -> 1 atomic instr per 16B.
// ---------------------------------------------------------------------------
__global__ void scatter_kernel(const float* __restrict__ x,
                               const int* __restrict__ src,
                               const int* __restrict__ dst,
                               float* __restrict__ agg) {
    long long idx = (long long)blockIdx.x * blockDim.x + threadIdx.x;
    int e    = (int)(idx >> 5);
    int lane = (int)(idx & 31);
    if (e >= NE) return;
    int s = __ldg(src + e);
    int d = __ldg(dst + e);
    float ns = rsqrtf(fmaxf(g_deg_out[s], 1.0f));
    float4 v = __ldg(((const float4*)(x + (size_t)s * 128)) + lane);
    float* p = agg + (size_t)d * 128 + lane * 4;
    asm volatile("red.global.add.v4.f32 [%0], {%1,%2,%3,%4};"
                 :: "l"(p), "f"(v.x * ns), "f"(v.y * ns),
                    "f"(v.z * ns), "f"(v.w * ns)
                 : "memory");
}

// ---------------------------------------------------------------------------
// GEMM: Y[row] = act( (X[row] * rsqrt(max(deg_in[row],1))) @ W + b )
// Block: 256 threads = 32 col-threads x 8 row-threads; tile 64 rows x F_OUT.
// Thread computes 8 rows x (F_OUT/32) cols in registers. W + x tile in smem.
// ---------------------------------------------------------------------------
template <int F_OUT, bool RELU>
__global__ void gemm_kernel(const float* __restrict__ X,     // [NN][128]
                            const float* __restrict__ W,     // [128][F_OUT]
                            const float* __restrict__ b,     // [F_OUT]
                            const float* __restrict__ deg_in,
                            float* __restrict__ Y) {         // [NN][F_OUT]
    constexpr int COLS_T = F_OUT / 32;  // 4 (F_OUT=128) or 2 (F_OUT=64)
    extern __shared__ float smem[];
    float* W_s = smem;                    // [128][F_OUT]
    float* x_s = W_s + 128 * F_OUT;       // [64][128]
    float* b_s = x_s + 64 * 128;          // [F_OUT]

    const int tid = threadIdx.x;

    // Load W (coalesced float4)
    for (int i = tid; i < 128 * F_OUT / 4; i += 256)
        ((float4*)W_s)[i] = ((const float4*)W)[i];
    if (tid < F_OUT) b_s[tid] = b[tid];

    // Load x tile, scaled by norm_dst
    const int row0 = blockIdx.x * 64;
    for (int i = tid; i < 64 * 128 / 4; i += 256) {
        int r   = i >> 5;       // 32 float4 per row
        int c4  = i & 31;
        int row = row0 + r;
        float4 v;
        if (row < NN) {
            v = __ldg(((const float4*)(X + (size_t)row * 128)) + c4);
            float nd = rsqrtf(fmaxf(deg_in[row], 1.0f));
            v.x *= nd; v.y *= nd; v.z *= nd; v.w *= nd;
        } else {
            v = make_float4(0.f, 0.f, 0.f, 0.f);
        }
        ((float4*)x_s)[i] = v;
    }
    __syncthreads();

    const int ct = tid & 31;   // column thread 0..31
    const int rt = tid >> 5;   // row thread 0..7

    float acc[8][COLS_T];
#pragma unroll
    for (int i = 0; i < 8; i++)
#pragma unroll
        for (int j = 0; j < COLS_T; j++) acc[i][j] = 0.f;

#pragma unroll 4
    for (int k = 0; k < 128; k++) {
        float w[COLS_T];
        if constexpr (COLS_T == 4) {
            float4 wv = ((const float4*)(W_s + k * F_OUT))[ct];
            w[0] = wv.x; w[1] = wv.y; w[2] = wv.z; w[3] = wv.w;
        } else {
            float2 wv = ((const float2*)(W_s + k * F_OUT))[ct];
            w[0] = wv.x; w[1] = wv.y;
        }
#pragma unroll
        for (int i = 0; i < 8; i++) {
            float xv = x_s[(rt * 8 + i) * 128 + k];  // warp-uniform broadcast
#pragma unroll
            for (int j = 0; j < COLS_T; j++)
                acc[i][j] = fmaf(xv, w[j], acc[i][j]);
        }
    }

#pragma unroll
    for (int i = 0; i < 8; i++) {
        int row = row0 + rt * 8 + i;
        if (row < NN) {
#pragma unroll
            for (int j = 0; j < COLS_T; j++) {
                float v = acc[i][j] + b_s[ct * COLS_T + j];
                if constexpr (RELU) v = fmaxf(v, 0.f);
                Y[(size_t)row * F_OUT + ct * COLS_T + j] = v;
            }
        }
    }
}

// ---------------------------------------------------------------------------
extern "C" void kernel_launch(void* const* d_in, const int* in_sizes, int n_in,
                              void* d_out, int out_size) {
    const float* x   = (const float*)d_in[0];
    const int*   src = (const int*)d_in[1];
    const int*   dst = (const int*)d_in[2];
    const float* W1  = (const float*)d_in[3];
    const float* b1  = (const float*)d_in[4];
    const float* W2  = (const float*)d_in[5];
    const float* b2  = (const float*)d_in[6];
    float* out = (float*)d_out;

    void *p_agg1, *p_agg2, *p_h, *p_din;
    cudaGetSymbolAddress(&p_agg1, g_agg1);
    cudaGetSymbolAddress(&p_agg2, g_agg2);
    cudaGetSymbolAddress(&p_h,    g_h);
    cudaGetSymbolAddress(&p_din,  g_deg_in);

    zero_kernel<<<2048, 256>>>();
    degree_kernel<<<(NE + 255) / 256, 256>>>(src, dst);

    // Layer 1
    scatter_kernel<<<(int)(((long long)NE * 32 + 255) / 256), 256>>>(
        x, src, dst, (float*)p_agg1);

    size_t sm1 = (size_t)(128 * F_HID + 64 * 128 + F_HID) * sizeof(float);
    cudaFuncSetAttribute(gemm_kernel<F_HID, true>,
                         cudaFuncAttributeMaxDynamicSharedMemorySize, (int)sm1);
    gemm_kernel<F_HID, true><<<(NN + 63) / 64, 256, sm1>>>(
        (const float*)p_agg1, W1, b1, (const float*)p_din, (float*)p_h);

    // Layer 2
    scatter_kernel<<<(int)(((long long)NE * 32 + 255) / 256), 256>>>(
        (const float*)p_h, src, dst, (float*)p_agg2);

    size_t sm2 = (size_t)(128 * F_CLS + 64 * 128 + F_CLS) * sizeof(float);
    cudaFuncSetAttribute(gemm_kernel<F_CLS, false>,
                         cudaFuncAttributeMaxDynamicSharedMemorySize, (int)sm2);
    gemm_kernel<F_CLS, false><<<(NN + 63) / 64, 256, sm2>>>(
        (const float*)p_agg2, W2, b2, (const float*)p_din, out);
}

// round 2
// speedup vs baseline: 2.1678x; 2.1678x over previous
#include <cuda_runtime.h>
#include <cuda_bf16.h>

#define NN 100000
#define NE 1600000
#define F_IN 128
#define F_HID 128
#define F_CLS 64
#define NBLK_SCAN 98   // ceil(NN/1024)

// ---- scratch (device globals; no allocs allowed) ----
__device__ int   g_cnt_in[NN];
__device__ int   g_cnt_out[NN];
__device__ int   g_row_ptr[NN + 1];
__device__ int   g_cursor[NN];
__device__ int   g_csr_src[NE];
__device__ float g_norm_in[NN];
__device__ float g_norm_out[NN];
__device__ int   g_bsum[NBLK_SCAN + 1];
__device__ float g_t1[(size_t)NN * F_HID];
__device__ float g_h [(size_t)NN * F_HID];
__device__ float g_t2[(size_t)NN * F_CLS];

// ---- f32x2 packed-math helpers (sm_10x) ----
__device__ __forceinline__ unsigned long long fma2(unsigned long long a,
                                                   unsigned long long b,
                                                   unsigned long long c) {
    unsigned long long d;
    asm("fma.rn.f32x2 %0, %1, %2, %3;" : "=l"(d) : "l"(a), "l"(b), "l"(c));
    return d;
}
__device__ __forceinline__ unsigned long long dup2(float x) {
    unsigned long long d;
    unsigned int xb = __float_as_uint(x);
    asm("mov.b64 %0, {%1, %1};" : "=l"(d) : "r"(xb));
    return d;
}
__device__ __forceinline__ float2 unpk(unsigned long long v) {
    unsigned int lo, hi;
    asm("mov.b64 {%0, %1}, %2;" : "=r"(lo), "=r"(hi) : "l"(v));
    return make_float2(__uint_as_float(lo), __uint_as_float(hi));
}

// ===========================================================================
// CSR build
// ===========================================================================
__global__ void zero_counts() {
    int i = blockIdx.x * blockDim.x + threadIdx.x;
    if (i < NN) { g_cnt_in[i] = 0; g_cnt_out[i] = 0; }
}

__global__ void count_kernel(const int* __restrict__ src,
                             const int* __restrict__ dst) {
    int e = blockIdx.x * blockDim.x + threadIdx.x;
    if (e < NE) {
        atomicAdd(&g_cnt_out[src[e]], 1);
        atomicAdd(&g_cnt_in[dst[e]], 1);
    }
}

__global__ void block_reduce_kernel() {   // grid = NBLK_SCAN, block = 1024
    __shared__ int s[1024];
    int t = threadIdx.x;
    int i = blockIdx.x * 1024 + t;
    s[t] = (i < NN) ? g_cnt_in[i] : 0;
    __syncthreads();
    for (int off = 512; off > 0; off >>= 1) {
        if (t < off) s[t] += s[t + off];
        __syncthreads();
    }
    if (t == 0) g_bsum[blockIdx.x] = s[0];
}

__global__ void scan_small_kernel() {     // 1 thread
    int run = 0;
    for (int b = 0; b < NBLK_SCAN; b++) {
        int v = g_bsum[b];
        g_bsum[b] = run;
        run += v;
    }
    g_row_ptr[NN] = NE;
}

__global__ void scan_apply_kernel() {     // grid = NBLK_SCAN, block = 1024
    __shared__ int s[1024];
    int t = threadIdx.x;
    int i = blockIdx.x * 1024 + t;
    int v = (i < NN) ? g_cnt_in[i] : 0;
    s[t] = v;
    __syncthreads();
    for (int off = 1; off < 1024; off <<= 1) {
        int add = (t >= off) ? s[t - off] : 0;
        __syncthreads();
        s[t] += add;
        __syncthreads();
    }
    if (i < NN) {
        int excl = s[t] - v + g_bsum[blockIdx.x];
        g_row_ptr[i] = excl;
        g_cursor[i]  = excl;
        g_norm_in[i]  = rsqrtf(fmaxf((float)v, 1.0f));
        g_norm_out[i] = rsqrtf(fmaxf((float)g_cnt_out[i], 1.0f));
    }
}

__global__ void fill_kernel(const int* __restrict__ src,
                            const int* __restrict__ dst) {
    int e = blockIdx.x * blockDim.x + threadIdx.x;
    if (e < NE) {
        int pos = atomicAdd(&g_cursor[dst[e]], 1);
        g_csr_src[pos] = src[e];
    }
}

// ===========================================================================
// GEMM: Y[row] = (X[row] @ W) * norm_out[row]      (no bias)
// 256 thr = 32 col-thr x 8 row-thr; 64-row tile; f32x2 packed FMA.
// ===========================================================================
template <int F_OUT>
__global__ void gemm_kernel(const float* __restrict__ X,   // [NN][128]
                            const float* __restrict__ W,   // [128][F_OUT]
                            float* __restrict__ Y) {       // [NN][F_OUT]
    constexpr int PAIRS = F_OUT / 64;  // u64 pairs per thread per k: 2 or 1
    extern __shared__ float smem[];
    float* W_s = smem;                  // [128][F_OUT]
    float* x_s = W_s + 128 * F_OUT;     // [64][128]

    const int tid = threadIdx.x;
    for (int i = tid; i < 128 * F_OUT / 4; i += 256)
        ((float4*)W_s)[i] = ((const float4*)W)[i];

    const int row0 = blockIdx.x * 64;
    for (int i = tid; i < 64 * 128 / 4; i += 256) {
        int r = i >> 5, c4 = i & 31;
        int row = row0 + r;
        float4 v = (row < NN)
            ? __ldg(((const float4*)(X + (size_t)row * 128)) + c4)
            : make_float4(0.f, 0.f, 0.f, 0.f);
        ((float4*)x_s)[i] = v;
    }
    __syncthreads();

    const int ct = tid & 31;
    const int rt = tid >> 5;

    unsigned long long acc[8][PAIRS];
#pragma unroll
    for (int i = 0; i < 8; i++)
#pragma unroll
        for (int j = 0; j < PAIRS; j++) acc[i][j] = 0ULL;

    for (int k = 0; k < 128; k += 4) {
        unsigned long long w[4][PAIRS];
#pragma unroll
        for (int kk = 0; kk < 4; kk++) {
            if constexpr (PAIRS == 2) {
                ulonglong2 wv = ((const ulonglong2*)(W_s + (k + kk) * F_OUT))[ct];
                w[kk][0] = wv.x; w[kk][1] = wv.y;
            } else {
                w[kk][0] = ((const unsigned long long*)(W_s + (k + kk) * F_OUT))[ct];
            }
        }
#pragma unroll
        for (int i = 0; i < 8; i++) {
            float4 xv = *((const float4*)(x_s + (rt * 8 + i) * 128 + k));
            float xa0 = xv.x, xa1 = xv.y, xa2 = xv.z, xa3 = xv.w;
            unsigned long long xx;
            xx = dup2(xa0);
#pragma unroll
            for (int j = 0; j < PAIRS; j++) acc[i][j] = fma2(xx, w[0][j], acc[i][j]);
            xx = dup2(xa1);
#pragma unroll
            for (int j = 0; j < PAIRS; j++) acc[i][j] = fma2(xx, w[1][j], acc[i][j]);
            xx = dup2(xa2);
#pragma unroll
            for (int j = 0; j < PAIRS; j++) acc[i][j] = fma2(xx, w[2][j], acc[i][j]);
            xx = dup2(xa3);
#pragma unroll
            for (int j = 0; j < PAIRS; j++) acc[i][j] = fma2(xx, w[3][j], acc[i][j]);
        }
    }

#pragma unroll
    for (int i = 0; i < 8; i++) {
        int row = row0 + rt * 8 + i;
        if (row < NN) {
            float ns = __ldg(g_norm_out + row);
            if constexpr (PAIRS == 2) {
                float2 p0 = unpk(acc[i][0]), p1 = unpk(acc[i][1]);
                float4 o = make_float4(p0.x * ns, p0.y * ns, p1.x * ns, p1.y * ns);
                ((float4*)(Y + (size_t)row * F_OUT))[ct] = o;
            } else {
                float2 p0 = unpk(acc[i][0]);
                float2 o = make_float2(p0.x * ns, p0.y * ns);
                ((float2*)(Y + (size_t)row * F_OUT))[ct] = o;
            }
        }
    }
}

// ===========================================================================
// Gather (aggregate): warp per node.
//   out[n] = act( norm_in[n] * sum_{e in CSR(n)} T[csr_src[e]]  + b )
// F=128: float4/lane.  F=64: float2/lane.
// ===========================================================================
__global__ void gather128_relu_kernel(const float* __restrict__ T,
                                      const float* __restrict__ b,
                                      float* __restrict__ out) {
    int w = (blockIdx.x * blockDim.x + threadIdx.x) >> 5;
    int lane = threadIdx.x & 31;
    if (w >= NN) return;
    int beg = g_row_ptr[w], end = g_row_ptr[w + 1];
    float4 acc = make_float4(0.f, 0.f, 0.f, 0.f);
    int i = beg;
    for (; i + 1 < end; i += 2) {
        int s0 = __ldg(g_csr_src + i);
        int s1 = __ldg(g_csr_src + i + 1);
        float4 v0 = __ldg(((const float4*)(T + (size_t)s0 * 128)) + lane);
        float4 v1 = __ldg(((const float4*)(T + (size_t)s1 * 128)) + lane);
        acc.x += v0.x + v1.x; acc.y += v0.y + v1.y;
        acc.z += v0.z + v1.z; acc.w += v0.w + v1.w;
    }
    if (i < end) {
        int s0 = __ldg(g_csr_src + i);
        float4 v0 = __ldg(((const float4*)(T + (size_t)s0 * 128)) + lane);
        acc.x += v0.x; acc.y += v0.y; acc.z += v0.z; acc.w += v0.w;
    }
    float nd = g_norm_in[w];
    float4 bb = __ldg(((const float4*)b) + lane);
    float4 o;
    o.x = fmaxf(fmaf(acc.x, nd, bb.x), 0.f);
    o.y = fmaxf(fmaf(acc.y, nd, bb.y), 0.f);
    o.z = fmaxf(fmaf(acc.z, nd, bb.z), 0.f);
    o.w = fmaxf(fmaf(acc.w, nd, bb.w), 0.f);
    ((float4*)(out + (size_t)w * 128))[lane] = o;
}

__global__ void gather64_kernel(const float* __restrict__ T,
                                const float* __restrict__ b,
                                float* __restrict__ out) {
    int w = (blockIdx.x * blockDim.x + threadIdx.x) >> 5;
    int lane = threadIdx.x & 31;
    if (w >= NN) return;
    int beg = g_row_ptr[w], end = g_row_ptr[w + 1];
    float2 acc = make_float2(0.f, 0.f);
    int i = beg;
    for (; i + 1 < end; i += 2) {
        int s0 = __ldg(g_csr_src + i);
        int s1 = __ldg(g_csr_src + i + 1);
        float2 v0 = __ldg(((const float2*)(T + (size_t)s0 * 64)) + lane);
        float2 v1 = __ldg(((const float2*)(T + (size_t)s1 * 64)) + lane);
        acc.x += v0.x + v1.x; acc.y += v0.y + v1.y;
    }
    if (i < end) {
        int s0 = __ldg(g_csr_src + i);
        float2 v0 = __ldg(((const float2*)(T + (size_t)s0 * 64)) + lane);
        acc.x += v0.x; acc.y += v0.y;
    }
    float nd = g_norm_in[w];
    float2 bb = __ldg(((const float2*)b) + lane);
    float2 o;
    o.x = fmaf(acc.x, nd, bb.x);
    o.y = fmaf(acc.y, nd, bb.y);
    ((float2*)(out + (size_t)w * 64))[lane] = o;
}

// ===========================================================================
extern "C" void kernel_launch(void* const* d_in, const int* in_sizes, int n_in,
                              void* d_out, int out_size) {
    const float* x   = (const float*)d_in[0];
    const int*   src = (const int*)d_in[1];
    const int*   dst = (const int*)d_in[2];
    const float* W1  = (const float*)d_in[3];
    const float* b1  = (const float*)d_in[4];
    const float* W2  = (const float*)d_in[5];
    const float* b2  = (const float*)d_in[6];
    float* out = (float*)d_out;

    void *p_t1, *p_t2, *p_h;
    cudaGetSymbolAddress(&p_t1, g_t1);
    cudaGetSymbolAddress(&p_t2, g_t2);
    cudaGetSymbolAddress(&p_h,  g_h);

    // CSR build + norms
    zero_counts<<<(NN + 255) / 256, 256>>>();
    count_kernel<<<(NE + 255) / 256, 256>>>(src, dst);
    block_reduce_kernel<<<NBLK_SCAN, 1024>>>();
    scan_small_kernel<<<1, 1>>>();
    scan_apply_kernel<<<NBLK_SCAN, 1024>>>();
    fill_kernel<<<(NE + 255) / 256, 256>>>(src, dst);

    // Layer 1: t1 = (x@W1)*norm_out ; h = relu(norm_in * agg(t1) + b1)
    size_t sm1 = (size_t)(128 * F_HID + 64 * 128) * sizeof(float);
    cudaFuncSetAttribute(gemm_kernel<F_HID>,
                         cudaFuncAttributeMaxDynamicSharedMemorySize, (int)sm1);
    gemm_kernel<F_HID><<<(NN + 63) / 64, 256, sm1>>>(x, W1, (float*)p_t1);
    gather128_relu_kernel<<<(NN * 32 + 255) / 256, 256>>>(
        (const float*)p_t1, b1, (float*)p_h);

    // Layer 2: t2 = (h@W2)*norm_out ; out = norm_in * agg(t2) + b2
    size_t sm2 = (size_t)(128 * F_CLS + 64 * 128) * sizeof(float);
    cudaFuncSetAttribute(gemm_kernel<F_CLS>,
                         cudaFuncAttributeMaxDynamicSharedMemorySize, (int)sm2);
    gemm_kernel<F_CLS><<<(NN + 63) / 64, 256, sm2>>>(
        (const float*)p_h, W2, (float*)p_t2);
    gather64_kernel<<<(NN * 32 + 255) / 256, 256>>>(
        (const float*)p_t2, b2, out);
}

// round 4
// speedup vs baseline: 2.3678x; 1.0922x over previous
#include <cuda_runtime.h>
#include <cuda_fp16.h>

#define NN 100000
#define NE 1600000
#define F_IN 128
#define F_HID 128
#define F_CLS 64
#define NBLK_SCAN 98            // ceil(NN/1024)
#define GB1 ((NN + 63) / 64)    // gemm1 tile blocks = 1563
#define FILL_BLOCKS 1024

// ---- scratch (device globals; no allocs allowed) ----
__device__ int    g_cnt_in[NN];
__device__ int    g_cnt_out[NN];
__device__ int    g_row_ptr[NN + 1];
__device__ int    g_cursor[NN];
__device__ int    g_csr_src[NE];
__device__ float  g_norm_in[NN];
__device__ float  g_norm_out[NN];
__device__ int    g_bsum[NBLK_SCAN + 1];
__device__ __half g_t1[(size_t)NN * F_HID];   // fp16 intermediate
__device__ float  g_h [(size_t)NN * F_HID];
__device__ __half g_t2[(size_t)NN * F_CLS];   // fp16 intermediate

// ---- fp16 vector load helpers (via uint __ldg overloads) ----
__device__ __forceinline__ void ldg_h4_f(const __half* p, float2& lo, float2& hi) {
    uint2 raw = __ldg((const uint2*)p);
    lo = __half22float2(*(const __half2*)&raw.x);
    hi = __half22float2(*(const __half2*)&raw.y);
}
__device__ __forceinline__ float2 ldg_h2_f(const __half* p) {
    unsigned int raw = __ldg((const unsigned int*)p);
    return __half22float2(*(const __half2*)&raw);
}

struct alignas(8) half4 { __half2 a, b; };

// ---- f32x2 packed-math helpers (sm_10x) ----
__device__ __forceinline__ unsigned long long fma2(unsigned long long a,
                                                   unsigned long long b,
                                                   unsigned long long c) {
    unsigned long long d;
    asm("fma.rn.f32x2 %0, %1, %2, %3;" : "=l"(d) : "l"(a), "l"(b), "l"(c));
    return d;
}
__device__ __forceinline__ unsigned long long dup2(float x) {
    unsigned long long d;
    unsigned int xb = __float_as_uint(x);
    asm("mov.b64 %0, {%1, %1};" : "=l"(d) : "r"(xb));
    return d;
}
__device__ __forceinline__ float2 unpk(unsigned long long v) {
    unsigned int lo, hi;
    asm("mov.b64 {%0, %1}, %2;" : "=r"(lo), "=r"(hi) : "l"(v));
    return make_float2(__uint_as_float(lo), __uint_as_float(hi));
}

// ===========================================================================
// CSR build
// ===========================================================================
__global__ void zero_counts() {
    int stride = gridDim.x * blockDim.x;
    for (int i = blockIdx.x * blockDim.x + threadIdx.x; i < NN; i += stride) {
        g_cnt_in[i] = 0; g_cnt_out[i] = 0;
    }
}

__global__ void count_kernel(const int* __restrict__ src,
                             const int* __restrict__ dst) {
    int e = blockIdx.x * blockDim.x + threadIdx.x;
    if (e < NE) {
        atomicAdd(&g_cnt_out[src[e]], 1);
        atomicAdd(&g_cnt_in[dst[e]], 1);
    }
}

__global__ void block_reduce_kernel() {   // grid = NBLK_SCAN, block = 1024
    __shared__ int s[1024];
    int t = threadIdx.x;
    int i = blockIdx.x * 1024 + t;
    s[t] = (i < NN) ? g_cnt_in[i] : 0;
    __syncthreads();
    for (int off = 512; off > 0; off >>= 1) {
        if (t < off) s[t] += s[t + off];
        __syncthreads();
    }
    if (t == 0) g_bsum[blockIdx.x] = s[0];
}

__global__ void scan_small_kernel() {     // 1 block, 128 threads
    __shared__ int s[128];
    int t = threadIdx.x;
    int v = (t < NBLK_SCAN) ? g_bsum[t] : 0;
    s[t] = v;
    __syncthreads();
    for (int off = 1; off < 128; off <<= 1) {
        int add = (t >= off) ? s[t - off] : 0;
        __syncthreads();
        s[t] += add;
        __syncthreads();
    }
    if (t < NBLK_SCAN) g_bsum[t] = s[t] - v;   // exclusive
    if (t == 0) g_row_ptr[NN] = NE;
}

__global__ void scan_apply_kernel() {     // grid = NBLK_SCAN, block = 1024
    __shared__ int s[1024];
    int t = threadIdx.x;
    int i = blockIdx.x * 1024 + t;
    int v = (i < NN) ? g_cnt_in[i] : 0;
    s[t] = v;
    __syncthreads();
    for (int off = 1; off < 1024; off <<= 1) {
        int add = (t >= off) ? s[t - off] : 0;
        __syncthreads();
        s[t] += add;
        __syncthreads();
    }
    if (i < NN) {
        int excl = s[t] - v + g_bsum[blockIdx.x];
        g_row_ptr[i] = excl;
        g_cursor[i]  = excl;
        g_norm_in[i]  = rsqrtf(fmaxf((float)v, 1.0f));
        g_norm_out[i] = rsqrtf(fmaxf((float)g_cnt_out[i], 1.0f));
    }
}

// ===========================================================================
// FUSED: gemm1 (blocks [0,GB1)) + CSR fill (blocks [GB1, GB1+FILL_BLOCKS))
// gemm1: t1[row] = half( (x[row] @ W1) * norm_out[row] )
// ===========================================================================
__global__ void fused_gemm1_fill_kernel(const float* __restrict__ X,
                                        const float* __restrict__ W,
                                        __half* __restrict__ Y,
                                        const int* __restrict__ src,
                                        const int* __restrict__ dst) {
    const int tid = threadIdx.x;
    if (blockIdx.x >= GB1) {
        // ---- fill role ----
        int e0 = (blockIdx.x - GB1) * 256 + tid;
        for (int e = e0; e < NE; e += 256 * FILL_BLOCKS) {
            int pos = atomicAdd(&g_cursor[dst[e]], 1);
            g_csr_src[pos] = src[e];
        }
        return;
    }
    // ---- gemm role (F_OUT = 128, PAIRS = 2) ----
    extern __shared__ float smem[];
    float* W_s = smem;                  // [128][128]
    float* x_s = W_s + 128 * 128;       // [64][128]

    for (int i = tid; i < 128 * 128 / 4; i += 256)
        ((float4*)W_s)[i] = ((const float4*)W)[i];

    const int row0 = blockIdx.x * 64;
    for (int i = tid; i < 64 * 128 / 4; i += 256) {
        int r = i >> 5, c4 = i & 31;
        int row = row0 + r;
        float4 v = (row < NN)
            ? __ldg(((const float4*)(X + (size_t)row * 128)) + c4)
            : make_float4(0.f, 0.f, 0.f, 0.f);
        ((float4*)x_s)[i] = v;
    }
    __syncthreads();

    const int ct = tid & 31;
    const int rt = tid >> 5;

    unsigned long long acc[8][2];
#pragma unroll
    for (int i = 0; i < 8; i++) { acc[i][0] = 0ULL; acc[i][1] = 0ULL; }

    for (int k = 0; k < 128; k += 4) {
        unsigned long long w[4][2];
#pragma unroll
        for (int kk = 0; kk < 4; kk++) {
            ulonglong2 wv = ((const ulonglong2*)(W_s + (k + kk) * 128))[ct];
            w[kk][0] = wv.x; w[kk][1] = wv.y;
        }
#pragma unroll
        for (int i = 0; i < 8; i++) {
            float4 xv = *((const float4*)(x_s + (rt * 8 + i) * 128 + k));
            unsigned long long xx;
            xx = dup2(xv.x);
            acc[i][0] = fma2(xx, w[0][0], acc[i][0]);
            acc[i][1] = fma2(xx, w[0][1], acc[i][1]);
            xx = dup2(xv.y);
            acc[i][0] = fma2(xx, w[1][0], acc[i][0]);
            acc[i][1] = fma2(xx, w[1][1], acc[i][1]);
            xx = dup2(xv.z);
            acc[i][0] = fma2(xx, w[2][0], acc[i][0]);
            acc[i][1] = fma2(xx, w[2][1], acc[i][1]);
            xx = dup2(xv.w);
            acc[i][0] = fma2(xx, w[3][0], acc[i][0]);
            acc[i][1] = fma2(xx, w[3][1], acc[i][1]);
        }
    }

#pragma unroll
    for (int i = 0; i < 8; i++) {
        int row = row0 + rt * 8 + i;
        if (row < NN) {
            float ns = __ldg(g_norm_out + row);
            float2 p0 = unpk(acc[i][0]), p1 = unpk(acc[i][1]);
            half4 o;
            o.a = __floats2half2_rn(p0.x * ns, p0.y * ns);
            o.b = __floats2half2_rn(p1.x * ns, p1.y * ns);
            ((half4*)(Y + (size_t)row * 128))[ct] = o;
        }
    }
}

// ===========================================================================
// gemm2: t2[row] = half( (h[row] @ W2) * norm_out[row] )   (F_OUT = 64)
// ===========================================================================
__global__ void gemm2_kernel(const float* __restrict__ X,
                             const float* __restrict__ W,
                             __half* __restrict__ Y) {
    extern __shared__ float smem[];
    float* W_s = smem;                  // [128][64]
    float* x_s = W_s + 128 * 64;        // [64][128]

    const int tid = threadIdx.x;
    for (int i = tid; i < 128 * 64 / 4; i += 256)
        ((float4*)W_s)[i] = ((const float4*)W)[i];

    const int row0 = blockIdx.x * 64;
    for (int i = tid; i < 64 * 128 / 4; i += 256) {
        int r = i >> 5, c4 = i & 31;
        int row = row0 + r;
        float4 v = (row < NN)
            ? __ldg(((const float4*)(X + (size_t)row * 128)) + c4)
            : make_float4(0.f, 0.f, 0.f, 0.f);
        ((float4*)x_s)[i] = v;
    }
    __syncthreads();

    const int ct = tid & 31;
    const int rt = tid >> 5;

    unsigned long long acc[8];
#pragma unroll
    for (int i = 0; i < 8; i++) acc[i] = 0ULL;

    for (int k = 0; k < 128; k += 4) {
        unsigned long long w[4];
#pragma unroll
        for (int kk = 0; kk < 4; kk++)
            w[kk] = ((const unsigned long long*)(W_s + (k + kk) * 64))[ct];
#pragma unroll
        for (int i = 0; i < 8; i++) {
            float4 xv = *((const float4*)(x_s + (rt * 8 + i) * 128 + k));
            acc[i] = fma2(dup2(xv.x), w[0], acc[i]);
            acc[i] = fma2(dup2(xv.y), w[1], acc[i]);
            acc[i] = fma2(dup2(xv.z), w[2], acc[i]);
            acc[i] = fma2(dup2(xv.w), w[3], acc[i]);
        }
    }

#pragma unroll
    for (int i = 0; i < 8; i++) {
        int row = row0 + rt * 8 + i;
        if (row < NN) {
            float ns = __ldg(g_norm_out + row);
            float2 p = unpk(acc[i]);
            ((__half2*)(Y + (size_t)row * 64))[ct] =
                __floats2half2_rn(p.x * ns, p.y * ns);
        }
    }
}

// ===========================================================================
// Gathers: warp per node, fp16 in, fp32 accumulate.
// ===========================================================================
__global__ void gather128_relu_kernel(const __half* __restrict__ T,
                                      const float* __restrict__ b,
                                      float* __restrict__ out) {
    int w = (blockIdx.x * blockDim.x + threadIdx.x) >> 5;
    int lane = threadIdx.x & 31;
    if (w >= NN) return;
    int beg = g_row_ptr[w], end = g_row_ptr[w + 1];
    float4 acc = make_float4(0.f, 0.f, 0.f, 0.f);
    int i = beg;
    for (; i + 1 < end; i += 2) {
        int s0 = __ldg(g_csr_src + i);
        int s1 = __ldg(g_csr_src + i + 1);
        float2 a0, b0, a1, b1_;
        ldg_h4_f(T + (size_t)s0 * 128 + lane * 4, a0, b0);
        ldg_h4_f(T + (size_t)s1 * 128 + lane * 4, a1, b1_);
        acc.x += a0.x + a1.x; acc.y += a0.y + a1.y;
        acc.z += b0.x + b1_.x; acc.w += b0.y + b1_.y;
    }
    if (i < end) {
        int s0 = __ldg(g_csr_src + i);
        float2 a0, b0;
        ldg_h4_f(T + (size_t)s0 * 128 + lane * 4, a0, b0);
        acc.x += a0.x; acc.y += a0.y; acc.z += b0.x; acc.w += b0.y;
    }
    float nd = g_norm_in[w];
    float4 bb = __ldg(((const float4*)b) + lane);
    float4 o;
    o.x = fmaxf(fmaf(acc.x, nd, bb.x), 0.f);
    o.y = fmaxf(fmaf(acc.y, nd, bb.y), 0.f);
    o.z = fmaxf(fmaf(acc.z, nd, bb.z), 0.f);
    o.w = fmaxf(fmaf(acc.w, nd, bb.w), 0.f);
    ((float4*)(out + (size_t)w * 128))[lane] = o;
}

__global__ void gather64_kernel(const __half* __restrict__ T,
                                const float* __restrict__ b,
                                float* __restrict__ out) {
    int w = (blockIdx.x * blockDim.x + threadIdx.x) >> 5;
    int lane = threadIdx.x & 31;
    if (w >= NN) return;
    int beg = g_row_ptr[w], end = g_row_ptr[w + 1];
    float2 acc = make_float2(0.f, 0.f);
    int i = beg;
    for (; i + 1 < end; i += 2) {
        int s0 = __ldg(g_csr_src + i);
        int s1 = __ldg(g_csr_src + i + 1);
        float2 f0 = ldg_h2_f(T + (size_t)s0 * 64 + lane * 2);
        float2 f1 = ldg_h2_f(T + (size_t)s1 * 64 + lane * 2);
        acc.x += f0.x + f1.x; acc.y += f0.y + f1.y;
    }
    if (i < end) {
        int s0 = __ldg(g_csr_src + i);
        float2 f0 = ldg_h2_f(T + (size_t)s0 * 64 + lane * 2);
        acc.x += f0.x; acc.y += f0.y;
    }
    float nd = g_norm_in[w];
    float2 bb = __ldg(((const float2*)b) + lane);
    float2 o;
    o.x = fmaf(acc.x, nd, bb.x);
    o.y = fmaf(acc.y, nd, bb.y);
    ((float2*)(out + (size_t)w * 64))[lane] = o;
}

// ===========================================================================
extern "C" void kernel_launch(void* const* d_in, const int* in_sizes, int n_in,
                              void* d_out, int out_size) {
    const float* x   = (const float*)d_in[0];
    const int*   src = (const int*)d_in[1];
    const int*   dst = (const int*)d_in[2];
    const float* W1  = (const float*)d_in[3];
    const float* b1  = (const float*)d_in[4];
    const float* W2  = (const float*)d_in[5];
    const float* b2  = (const float*)d_in[6];
    float* out = (float*)d_out;

    void *p_t1, *p_t2, *p_h;
    cudaGetSymbolAddress(&p_t1, g_t1);
    cudaGetSymbolAddress(&p_t2, g_t2);
    cudaGetSymbolAddress(&p_h,  g_h);

    // CSR build (counts -> scan -> norms); fill is fused with gemm1 below.
    zero_counts<<<200, 256>>>();
    count_kernel<<<(NE + 255) / 256, 256>>>(src, dst);
    block_reduce_kernel<<<NBLK_SCAN, 1024>>>();
    scan_small_kernel<<<1, 128>>>();
    scan_apply_kernel<<<NBLK_SCAN, 1024>>>();

    // Layer 1 GEMM fused with CSR fill
    size_t sm1 = (size_t)(128 * 128 + 64 * 128) * sizeof(float);
    cudaFuncSetAttribute(fused_gemm1_fill_kernel,
                         cudaFuncAttributeMaxDynamicSharedMemorySize, (int)sm1);
    fused_gemm1_fill_kernel<<<GB1 + FILL_BLOCKS, 256, sm1>>>(
        x, W1, (__half*)p_t1, src, dst);

    gather128_relu_kernel<<<(NN * 32 + 255) / 256, 256>>>(
        (const __half*)p_t1, b1, (float*)p_h);

    // Layer 2
    size_t sm2 = (size_t)(128 * 64 + 64 * 128) * sizeof(float);
    cudaFuncSetAttribute(gemm2_kernel,
                         cudaFuncAttributeMaxDynamicSharedMemorySize, (int)sm2);
    gemm2_kernel<<<(NN + 63) / 64, 256, sm2>>>(
        (const float*)p_h, W2, (__half*)p_t2);

    gather64_kernel<<<(NN * 32 + 255) / 256, 256>>>(
        (const __half*)p_t2, b2, out);
}